// round 16
// baseline (speedup 1.0000x reference)
#include <cuda_runtime.h>
#include <cuda_bf16.h>
#include <cuda_fp16.h>
#include <math.h>
#include <stdint.h>

#define B_     64
#define T_     127
#define S_     128
#define ENC_   2048
#define EMB_   512
#define HID_   512
#define VOCAB_ 10000
#define MS_    (B_*S_)          // 8192
#define VPAD_  10112            // 79*128
#define KSPL_  1536             // bf16 3-term K'
#define KF16_  512              // fp16 single-term K' (fc2)

// ---------------- static scratch (no cudaMalloc allowed) ----------------
__device__ float g_fc1p[8*B_*EMB_];
__device__ float g_xw  [B_*S_*4*HID_];
__device__ float g_out [B_*S_*HID_];
__device__ float g_sc  [B_*S_*S_];
__device__ unsigned g_bar;
__device__ __nv_bfloat16 g_hh[2][B_*HID_];        // h hi (bf16), double buffered
__device__ __nv_bfloat16 g_hl[2][B_*HID_];        // h lo (bf16)
__device__ __nv_bfloat16 g_sbf  [MS_  * KSPL_];   // seq split   [Ah|Ah|Al]
__device__ __nv_bfloat16 g_wihbf[2048 * KSPL_];   // w_ih split  [Bh|Bl|Bh]
__device__ __nv_bfloat16 g_oA   [MS_  * KSPL_];   // masked out  [Oh|Oh|Ol]
__device__ __nv_bfloat16 g_oB   [MS_  * KSPL_];   // masked out  [Oh|Ol|Oh]
__device__ __half        g_af16 [MS_  * KF16_];   // attn fp16
__device__ __half        g_wf16 [VPAD_* KF16_];   // fc2_w fp16

__device__ __forceinline__ float sigmoidf_(float x) { return 1.f / (1.f + expf(-x)); }

__device__ __forceinline__ uint32_t smem_u32(const void* p) {
    uint32_t a;
    asm("{ .reg .u64 t; cvta.to.shared.u64 t, %1; cvt.u32.u64 %0, t; }" : "=r"(a) : "l"(p));
    return a;
}
__device__ __forceinline__ uint32_t pack_bf2(__nv_bfloat16 a, __nv_bfloat16 b) {
    return ((uint32_t)__bfloat16_as_ushort(b) << 16) | (uint32_t)__bfloat16_as_ushort(a);
}
__device__ __forceinline__ uint32_t pack_hf2(__half a, __half b) {
    return ((uint32_t)__half_as_ushort(b) << 16) | (uint32_t)__half_as_ushort(a);
}
#define CP_ASYNC16(dst, src) asm volatile("cp.async.cg.shared.global [%0], [%1], 16;" :: "r"(dst), "l"(src) : "memory")
#define CP_COMMIT()          asm volatile("cp.async.commit_group;" ::: "memory")
#define CP_WAIT1()           asm volatile("cp.async.wait_group 1;" ::: "memory")
#define CP_WAIT0()           asm volatile("cp.async.wait_group 0;" ::: "memory")

#define MMA_BF16(acc, a0, a1, a2, a3, b0, b1)                                    \
    asm volatile(                                                                \
        "mma.sync.aligned.m16n8k16.row.col.f32.bf16.bf16.f32 "                   \
        "{%0,%1,%2,%3}, {%4,%5,%6,%7}, {%8,%9}, {%0,%1,%2,%3};"                  \
        : "+f"(acc[0]), "+f"(acc[1]), "+f"(acc[2]), "+f"(acc[3])                 \
        : "r"(a0), "r"(a1), "r"(a2), "r"(a3), "r"(b0), "r"(b1))

#define MMA_F16(acc, a0, a1, a2, a3, b0, b1)                                     \
    asm volatile(                                                                \
        "mma.sync.aligned.m16n8k16.row.col.f32.f16.f16.f32 "                     \
        "{%0,%1,%2,%3}, {%4,%5,%6,%7}, {%8,%9}, {%0,%1,%2,%3};"                  \
        : "+f"(acc[0]), "+f"(acc[1]), "+f"(acc[2]), "+f"(acc[3])                 \
        : "r"(a0), "r"(a1), "r"(a2), "r"(a3), "r"(b0), "r"(b1))

// ============ warp-MMA NT GEMM, BK=64, dyn smem 64KB (validated) ==========
template <int FP16>
__global__ __launch_bounds__(256)
void gemm_mma(const uint16_t* __restrict__ A,
              const uint16_t* __restrict__ Bm,
              const float* __restrict__ bias1,
              const float* __restrict__ bias2,
              float* __restrict__ C, int Nreal, int ldc, int kelems,
              size_t sA_, size_t sB_, size_t sC_)
{
    extern __shared__ __align__(16) uint16_t smg[];

    A  += (size_t)blockIdx.z * sA_;
    Bm += (size_t)blockIdx.z * sB_;
    C  += (size_t)blockIdx.z * sC_;

    const int tid  = threadIdx.x;
    const int warp = tid >> 5;
    const int lane = tid & 31;
    const int wm0  = (warp & 3) * 32;
    const int wn0  = (warp >> 2) * 64;
    const int bm   = blockIdx.y * 128;
    const int bn   = blockIdx.x * 128;

    const uint32_t base0 = smem_u32(smg);

    float acc[2][8][4];
#pragma unroll
    for (int mt = 0; mt < 2; mt++)
#pragma unroll
        for (int nt = 0; nt < 8; nt++)
#pragma unroll
            for (int u = 0; u < 4; u++) acc[mt][nt][u] = 0.f;

#define LOAD_TILE(buf, c)                                                        \
    {                                                                            \
        _Pragma("unroll")                                                        \
        for (int u = 0; u < 4; u++) {                                            \
            int idx = tid * 4 + u;                                               \
            int r = idx >> 3, ch = idx & 7;                                      \
            int ph = ch ^ (r & 7);                                               \
            CP_ASYNC16(base0 + (buf) * 32768u + (uint32_t)(r * 8 + ph) * 16,     \
                       A + (size_t)(bm + r) * kelems + (c) * 64 + ch * 8);       \
            CP_ASYNC16(base0 + (buf) * 32768u + 16384u + (uint32_t)(r * 8 + ph) * 16, \
                       Bm + (size_t)(bn + r) * kelems + (c) * 64 + ch * 8);      \
        }                                                                        \
    }

    const int NCH = kelems >> 6;
    LOAD_TILE(0, 0);
    CP_COMMIT();

    for (int c = 0; c < NCH; c++) {
        const int buf = c & 1;
        if (c < NCH - 1) {
            LOAD_TILE(1 - buf, c + 1);
            CP_COMMIT();
            CP_WAIT1();
        } else {
            CP_WAIT0();
        }
        __syncthreads();

        const uint32_t aB = base0 + buf * 32768u;
        const uint32_t bB = aB + 16384u;

#pragma unroll
        for (int kc = 0; kc < 4; kc++) {
            uint32_t afr[2][4], bfr[8][2];
#pragma unroll
            for (int mt = 0; mt < 2; mt++) {
                int row = wm0 + mt * 16 + (lane & 15);
                int ch  = kc * 2 + (lane >> 4);
                int ph  = ch ^ (row & 7);
                uint32_t addr = aB + (uint32_t)(row * 8 + ph) * 16;
                asm volatile("ldmatrix.sync.aligned.m8n8.x4.shared.b16 {%0,%1,%2,%3}, [%4];"
                             : "=r"(afr[mt][0]), "=r"(afr[mt][1]),
                               "=r"(afr[mt][2]), "=r"(afr[mt][3]) : "r"(addr));
            }
#pragma unroll
            for (int nt = 0; nt < 8; nt++) {
                int row = wn0 + nt * 8 + (lane & 7);
                int ch  = kc * 2 + ((lane >> 3) & 1);
                int ph  = ch ^ (row & 7);
                uint32_t addr = bB + (uint32_t)(row * 8 + ph) * 16;
                asm volatile("ldmatrix.sync.aligned.m8n8.x2.shared.b16 {%0,%1}, [%2];"
                             : "=r"(bfr[nt][0]), "=r"(bfr[nt][1]) : "r"(addr));
            }
#pragma unroll
            for (int mt = 0; mt < 2; mt++)
#pragma unroll
                for (int nt = 0; nt < 8; nt++) {
                    if (FP16) {
                        MMA_F16(acc[mt][nt], afr[mt][0], afr[mt][1], afr[mt][2], afr[mt][3],
                                bfr[nt][0], bfr[nt][1]);
                    } else {
                        MMA_BF16(acc[mt][nt], afr[mt][0], afr[mt][1], afr[mt][2], afr[mt][3],
                                 bfr[nt][0], bfr[nt][1]);
                    }
                }
        }
        __syncthreads();
    }

#pragma unroll
    for (int mt = 0; mt < 2; mt++) {
#pragma unroll
        for (int nt = 0; nt < 8; nt++) {
            int row = wm0 + mt * 16 + (lane >> 2);
            int col = wn0 + nt * 8 + (lane & 3) * 2;
            int n = bn + col;
#pragma unroll
            for (int h = 0; h < 2; h++) {
                int m = bm + row + h * 8;
                float vx = acc[mt][nt][h * 2 + 0];
                float vy = acc[mt][nt][h * 2 + 1];
                if (n + 1 < Nreal) {
                    float2 v;
                    v.x = vx; v.y = vy;
                    if (bias1) { v.x += bias1[n]; v.y += bias1[n + 1]; }
                    if (bias2) { v.x += bias2[n]; v.y += bias2[n + 1]; }
                    *(float2*)&C[(size_t)m * ldc + n] = v;
                } else if (n < Nreal) {
                    float v = vx;
                    if (bias1) v += bias1[n];
                    if (bias2) v += bias2[n];
                    C[(size_t)m * ldc + n] = v;
                }
            }
        }
    }
}

// ---------------- bf16 hi/lo split for w_ih ([Bh|Bl|Bh]) ------------------
__global__ void cvt_split_b(const float* __restrict__ src, __nv_bfloat16* __restrict__ dst,
                            int rows_real, int rows_pad)
{
    int i = blockIdx.x * blockDim.x + threadIdx.x;
    if (i >= rows_pad * 512) return;
    int r = i >> 9, k = i & 511;
    float a = (r < rows_real) ? src[(size_t)r * 512 + k] : 0.f;
    __nv_bfloat16 hi = __float2bfloat16(a);
    float lo = a - __bfloat162float(hi);
    size_t b = (size_t)r * KSPL_;
    dst[b + k]        = hi;
    dst[b + 512 + k]  = __float2bfloat16(lo);
    dst[b + 1024 + k] = hi;
}

// ---------------- fp16 weight for fc2 (single copy) -----------------------
__global__ void cvt_w_f16(const float* __restrict__ src, __half* __restrict__ dst,
                          int rows_real, int rows_pad)
{
    int i = blockIdx.x * blockDim.x + threadIdx.x;
    if (i >= rows_pad * 512) return;
    int r = i >> 9, k = i & 511;
    float a = (r < rows_real) ? src[(size_t)r * 512 + k] : 0.f;
    dst[(size_t)r * KF16_ + k] = __float2half(a);
}

// ---------------- out splits for scores GEMM (parallel) -------------------
__global__ void cvt_out_k()
{
    int i = blockIdx.x * blockDim.x + threadIdx.x;
    if (i >= MS_ * 512) return;
    int r = i >> 9, k = i & 511;
    float v = g_out[(size_t)r * 512 + k];
    __nv_bfloat16 hi = __float2bfloat16(v);
    __nv_bfloat16 lo = __float2bfloat16(v - __bfloat162float(hi));
    size_t b = (size_t)r * KSPL_;
    g_oA[b + k]        = hi;
    g_oA[b + 512 + k]  = hi;
    g_oA[b + 1024 + k] = lo;
    g_oB[b + k]        = hi;
    g_oB[b + 512 + k]  = lo;
    g_oB[b + 1024 + k] = hi;
}

// ---------------- fc1 split-K --------------------------------------------
__global__ __launch_bounds__(256)
void fc1_part(const float* __restrict__ x, const float* __restrict__ w)
{
    const int nt = blockIdx.x, kt = blockIdx.y;
    __shared__ float xs[64][68];
    __shared__ float ws[64][68];
    const int tid = threadIdx.x;
    const int ty = tid >> 4, tx = tid & 15;

    float acc[4][4];
#pragma unroll
    for (int i = 0; i < 4; i++)
#pragma unroll
        for (int j = 0; j < 4; j++) acc[i][j] = 0.f;

    for (int kc = 0; kc < 4; kc++) {
        int k0 = kt * 256 + kc * 64;
        for (int i = tid; i < 64 * 16; i += 256) {
            int r = i >> 4, c4 = (i & 15) * 4;
            *(float4*)&xs[r][c4] = *(const float4*)&x[(size_t)r * ENC_ + k0 + c4];
            *(float4*)&ws[r][c4] = *(const float4*)&w[(size_t)(nt * 64 + r) * ENC_ + k0 + c4];
        }
        __syncthreads();
#pragma unroll 8
        for (int k = 0; k < 64; k++) {
            float a[4], b[4];
#pragma unroll
            for (int i = 0; i < 4; i++) a[i] = xs[ty * 4 + i][k];
#pragma unroll
            for (int j = 0; j < 4; j++) b[j] = ws[tx * 4 + j][k];
#pragma unroll
            for (int i = 0; i < 4; i++)
#pragma unroll
                for (int j = 0; j < 4; j++) acc[i][j] += a[i] * b[j];
        }
        __syncthreads();
    }
#pragma unroll
    for (int i = 0; i < 4; i++)
#pragma unroll
        for (int j = 0; j < 4; j++)
            g_fc1p[((size_t)kt * B_ + ty * 4 + i) * EMB_ + nt * 64 + tx * 4 + j] = acc[i][j];
}

// ---------------- fc1 reduce + batchnorm -> seq[:,0,:] split (fused) ------
__global__ void bn_k(const float* __restrict__ b1,
                     const float* __restrict__ gamma, const float* __restrict__ beta)
{
    int j = blockIdx.x;
    int b = threadIdx.x;
    float v = b1[j];
#pragma unroll
    for (int kt = 0; kt < 8; kt++) v += g_fc1p[((size_t)kt * B_ + b) * EMB_ + j];
    __shared__ float s1[64], s2[64];
    s1[b] = v; s2[b] = v * v;
    __syncthreads();
    for (int off = 32; off > 0; off >>= 1) {
        if (b < off) { s1[b] += s1[b + off]; s2[b] += s2[b + off]; }
        __syncthreads();
    }
    float mu  = s1[0] * (1.f / 64.f);
    float var = s2[0] * (1.f / 64.f) - mu * mu;
    float r   = rsqrtf(var + 1e-5f);
    float a   = (v - mu) * r * gamma[j] + beta[j];
    __nv_bfloat16 hi = __float2bfloat16(a);
    __nv_bfloat16 lo = __float2bfloat16(a - __bfloat162float(hi));
    size_t base = (size_t)(b * S_) * KSPL_ + j;
    g_sbf[base]        = hi;
    g_sbf[base + 512]  = hi;
    g_sbf[base + 1024] = lo;
}

// ---------------- embedding gather -> seq split ([Ah|Ah|Al]) --------------
__global__ void embed_k(const int* __restrict__ y, const float* __restrict__ emb)
{
    int i = blockIdx.x * blockDim.x + threadIdx.x;
    if (i >= B_ * T_ * (EMB_ / 4)) return;
    int d4 = i & 127;
    int bt = i >> 7;
    int tt = bt % T_;
    int b  = bt / T_;
    int tok = y[b * T_ + tt];
    float4 v = ((const float4*)emb)[(size_t)tok * (EMB_ / 4) + d4];
    __nv_bfloat16 h0 = __float2bfloat16(v.x), h1 = __float2bfloat16(v.y);
    __nv_bfloat16 h2 = __float2bfloat16(v.z), h3 = __float2bfloat16(v.w);
    uint2 hp, lp;
    hp.x = pack_bf2(h0, h1); hp.y = pack_bf2(h2, h3);
    lp.x = pack_bf2(__float2bfloat16(v.x - __bfloat162float(h0)),
                    __float2bfloat16(v.y - __bfloat162float(h1)));
    lp.y = pack_bf2(__float2bfloat16(v.z - __bfloat162float(h2)),
                    __float2bfloat16(v.w - __bfloat162float(h3)));
    size_t base = (size_t)(b * S_ + 1 + tt) * KSPL_ + d4 * 4;
    *(uint2*)&g_sbf[base]        = hp;
    *(uint2*)&g_sbf[base + 512]  = hp;
    *(uint2*)&g_sbf[base + 1024] = lp;
}

// ---------------- zero h0 (bf16 hi/lo) / barrier --------------------------
__global__ void zero_k()
{
    int i = blockIdx.x * blockDim.x + threadIdx.x;
    if (i < B_ * HID_ / 2) {
        ((uint32_t*)&g_hh[0][0])[i] = 0u;
        ((uint32_t*)&g_hl[0][0])[i] = 0u;
    }
    if (i == 0) g_bar = 0u;
}

// ---------------- persistent LSTM: 64 blocks x 512 threads ----------------
// Block owns 8 h-cols (32 W-rows). Halves the per-step L2 h-broadcast
// (8MB vs 16MB) and barrier arrivals (64 vs 128); per-warp mma unchanged.
// Warp grid 4 mt (batches) x 4 nb (W-row octet). Same accumulation order
// per output as the 128-block version -> bitwise-identical results.
#define LW_STRIDE 520
__global__ __launch_bounds__(512)
void lstm_mma(const float* __restrict__ w_hh, const int* __restrict__ lengths)
{
    extern __shared__ __align__(16) char smraw[];
    __nv_bfloat16* Wh  = (__nv_bfloat16*)smraw;                 // 32 x 520
    __nv_bfloat16* Wl  = Wh + 32 * LW_STRIDE;                   // 32 x 520
    __nv_bfloat16* Ahs = Wl + 32 * LW_STRIDE;                   // 64 x 520
    __nv_bfloat16* Als = Ahs + 64 * LW_STRIDE;                  // 64 x 520
    float* sg = (float*)(Als + 64 * LW_STRIDE);                 // 64 x 33

    const int tid  = threadIdx.x;
    const int warp = tid >> 5;
    const int lane = tid & 31;
    const int j0   = blockIdx.x * 8;

    // stage + split W: 32 rows r = g*8+jl <- w_hh[g*512 + j0+jl][:]
    for (int i = tid; i < 32 * 512; i += 512) {
        int r = i >> 9, k = i & 511;
        int g = r >> 3, jl = r & 7;
        float w = w_hh[(size_t)(g * HID_ + j0 + jl) * HID_ + k];
        __nv_bfloat16 hi = __float2bfloat16(w);
        float lo = w - __bfloat162float(hi);
        Wh[r * LW_STRIDE + k] = hi;
        Wl[r * LW_STRIDE + k] = __float2bfloat16(lo);
    }

    const uint32_t ahA = smem_u32(Ahs), alA = smem_u32(Als);
    const uint32_t whA = smem_u32(Wh),  wlA = smem_u32(Wl);

    const int mt = warp & 3;        // batch tile (16 batches)
    const int nb = warp >> 2;       // W-row octet (rows nb*8..nb*8+7)

    const int cb  = tid >> 3;       // cell-update batch (0..63)
    const int cj  = tid & 7;        // cell-update column local (0..7)
    const int len = lengths[cb];
    float creg = 0.f;

    const float* xwp = g_xw + (size_t)cb * S_ * (4 * HID_) + j0 + cj;

    volatile unsigned* vbar = &g_bar;
    __syncthreads();

    for (int t = 0; t < S_; t++) {
        float xwi = __ldg(xwp + 0 * HID_);
        float xwf = __ldg(xwp + 1 * HID_);
        float xwg = __ldg(xwp + 2 * HID_);
        float xwo = __ldg(xwp + 3 * HID_);
        xwp += 4 * HID_;

        if (tid == 0) {
            unsigned target = 64u * (unsigned)t;
            while (*vbar < target) { }
        }
        __syncthreads();

        // stage h hi then h lo: 4096 16B chunks each, 8 per thread
        const char* hh = (const char*)g_hh[t & 1];
        const char* hl = (const char*)g_hl[t & 1];
#pragma unroll
        for (int u = 0; u < 8; u++) {
            int idx = tid + u * 512;
            int b = idx >> 6, c = idx & 63;
            CP_ASYNC16(ahA + (uint32_t)(b * 65 + c) * 16, hh + b * 1024 + c * 16);
        }
        CP_COMMIT();
#pragma unroll
        for (int u = 0; u < 8; u++) {
            int idx = tid + u * 512;
            int b = idx >> 6, c = idx & 63;
            CP_ASYNC16(alA + (uint32_t)(b * 65 + c) * 16, hl + b * 1024 + c * 16);
        }
        CP_COMMIT();

        float acc[4] = {0.f, 0.f, 0.f, 0.f};

        CP_WAIT1();
        __syncthreads();

        const int arow0 = mt * 16 + (lane & 15);
        const int asel  = lane >> 4;
        const int brow0 = nb * 8 + (lane & 7);
        const int bsel  = (lane >> 3) & 1;

#pragma unroll
        for (int pass = 0; pass < 2; pass++) {
            uint32_t bB = pass ? wlA : whA;
#pragma unroll 8
            for (int kk = 0; kk < 32; kk++) {
                uint32_t a0, a1, a2, a3, b0, b1;
                uint32_t aaddr = ahA + (uint32_t)(arow0 * 65 + kk * 2 + asel) * 16;
                asm volatile("ldmatrix.sync.aligned.m8n8.x4.shared.b16 {%0,%1,%2,%3}, [%4];"
                             : "=r"(a0), "=r"(a1), "=r"(a2), "=r"(a3) : "r"(aaddr));
                uint32_t baddr = bB + (uint32_t)(brow0 * 65 + kk * 2 + bsel) * 16;
                asm volatile("ldmatrix.sync.aligned.m8n8.x2.shared.b16 {%0,%1}, [%2];"
                             : "=r"(b0), "=r"(b1) : "r"(baddr));
                MMA_BF16(acc, a0, a1, a2, a3, b0, b1);
            }
        }

        CP_WAIT0();
        __syncthreads();

#pragma unroll 8
        for (int kk = 0; kk < 32; kk++) {
            uint32_t a0, a1, a2, a3, b0, b1;
            uint32_t aaddr = alA + (uint32_t)(arow0 * 65 + kk * 2 + asel) * 16;
            asm volatile("ldmatrix.sync.aligned.m8n8.x4.shared.b16 {%0,%1,%2,%3}, [%4];"
                         : "=r"(a0), "=r"(a1), "=r"(a2), "=r"(a3) : "r"(aaddr));
            uint32_t baddr = whA + (uint32_t)(brow0 * 65 + kk * 2 + bsel) * 16;
            asm volatile("ldmatrix.sync.aligned.m8n8.x2.shared.b16 {%0,%1}, [%2];"
                         : "=r"(b0), "=r"(b1) : "r"(baddr));
            MMA_BF16(acc, a0, a1, a2, a3, b0, b1);
        }

        {
            int row = mt * 16 + (lane >> 2);
            int col = nb * 8 + (lane & 3) * 2;
            sg[row * 33 + col]           = acc[0];
            sg[row * 33 + col + 1]       = acc[1];
            sg[(row + 8) * 33 + col]     = acc[2];
            sg[(row + 8) * 33 + col + 1] = acc[3];
        }
        __syncthreads();

        {
            float vi = sg[cb * 33 + 0 * 8 + cj] + xwi;
            float vf = sg[cb * 33 + 1 * 8 + cj] + xwf;
            float vg = sg[cb * 33 + 2 * 8 + cj] + xwg;
            float vo = sg[cb * 33 + 3 * 8 + cj] + xwo;
            float gi = sigmoidf_(vi);
            float gf = sigmoidf_(vf);
            float gg = tanhf(vg);
            float go = sigmoidf_(vo);
            float c  = gf * creg + gi * gg;
            creg = c;
            float h = go * tanhf(c);
            int j = j0 + cj;
            g_out[((size_t)cb * S_ + t) * HID_ + j] = (t < len) ? h : 0.f;
            __nv_bfloat16 hi = __float2bfloat16(h);
            float lo = h - __bfloat162float(hi);
            g_hh[(t + 1) & 1][cb * HID_ + j] = hi;
            g_hl[(t + 1) & 1][cb * HID_ + j] = __float2bfloat16(lo);
        }
        __threadfence();
        __syncthreads();
        if (tid == 0) atomicAdd(&g_bar, 1u);
    }
}

// ------- attn: fused masked softmax + AV, writes fp16 for fc2 -------------
__global__ __launch_bounds__(256)
void attn_mm()
{
    int b  = blockIdx.y;
    int t0 = blockIdx.x * 16;
    __shared__ float al[16][128];
    int tid  = threadIdx.x;
    int warp = tid >> 5;
    int lane = tid & 31;

    for (int i = tid; i < 16 * 128; i += 256)
        al[i >> 7][i & 127] = g_sc[((size_t)b * S_ + t0 + (i >> 7)) * S_ + (i & 127)];
    __syncthreads();

#pragma unroll
    for (int rr = 0; rr < 2; rr++) {
        int r = warp * 2 + rr;
        int t = t0 + r;
        float v[4];
#pragma unroll
        for (int u = 0; u < 4; u++) {
            int s = lane + u * 32;
            float x = al[r][s];
            v[u] = (s < t) ? x : 0.f;
        }
        float m = fmaxf(fmaxf(v[0], v[1]), fmaxf(v[2], v[3]));
#pragma unroll
        for (int off = 16; off > 0; off >>= 1)
            m = fmaxf(m, __shfl_xor_sync(0xffffffffu, m, off));
        float e[4], sum = 0.f;
#pragma unroll
        for (int u = 0; u < 4; u++) { e[u] = expf(v[u] - m); sum += e[u]; }
#pragma unroll
        for (int off = 16; off > 0; off >>= 1)
            sum += __shfl_xor_sync(0xffffffffu, sum, off);
        float inv = 1.f / sum;
#pragma unroll
        for (int u = 0; u < 4; u++) {
            int s = lane + u * 32;
            al[r][s] = (s < t) ? e[u] * inv : 0.f;
        }
    }
    __syncthreads();

    int d0 = tid * 2;
    float2 acc[16];
#pragma unroll
    for (int t = 0; t < 16; t++) acc[t] = make_float2(0.f, 0.f);

    for (int s = 0; s < 128; s++) {
        float2 o = *(const float2*)&g_out[((size_t)b * S_ + s) * HID_ + d0];
#pragma unroll
        for (int t = 0; t < 16; t++) {
            float a = al[t][s];
            acc[t].x += a * o.x;
            acc[t].y += a * o.y;
        }
    }
#pragma unroll
    for (int t = 0; t < 16; t++) {
        uint32_t hp = pack_hf2(__float2half(acc[t].x), __float2half(acc[t].y));
        *(uint32_t*)&g_af16[((size_t)b * S_ + t0 + t) * KF16_ + d0] = hp;
    }
}

// ---------------- launch --------------------------------------------------
extern "C" void kernel_launch(void* const* d_in, const int* in_sizes, int n_in,
                              void* d_out, int out_size)
{
    const float* x      = (const float*)d_in[0];
    const int*   y      = (const int*)  d_in[1];
    const int*   len    = (const int*)  d_in[2];
    const float* fc1_w  = (const float*)d_in[3];
    const float* fc1_b  = (const float*)d_in[4];
    const float* bn_g   = (const float*)d_in[5];
    const float* bn_b   = (const float*)d_in[6];
    const float* emb    = (const float*)d_in[7];
    const float* w_ih   = (const float*)d_in[8];
    const float* w_hh   = (const float*)d_in[9];
    const float* b_ih   = (const float*)d_in[10];
    const float* b_hh   = (const float*)d_in[11];
    const float* fc2_w  = (const float*)d_in[12];
    const float* fc2_b  = (const float*)d_in[13];
    float* out = (float*)d_out;

    float *p_xw, *p_sc;
    __nv_bfloat16 *p_sbf, *p_wihbf, *p_oA, *p_oB;
    __half *p_af16, *p_wf16;
    cudaGetSymbolAddress((void**)&p_xw,    g_xw);
    cudaGetSymbolAddress((void**)&p_sc,    g_sc);
    cudaGetSymbolAddress((void**)&p_sbf,   g_sbf);
    cudaGetSymbolAddress((void**)&p_wihbf, g_wihbf);
    cudaGetSymbolAddress((void**)&p_oA,    g_oA);
    cudaGetSymbolAddress((void**)&p_oB,    g_oB);
    cudaGetSymbolAddress((void**)&p_af16,  g_af16);
    cudaGetSymbolAddress((void**)&p_wf16,  g_wf16);

    // smem: (32+32+64+64)*520*2 + 64*33*4 = 208128 B
    const int LSTM_SMEM = (32 + 32 + 64 + 64) * LW_STRIDE * 2 + 64 * 33 * 4;
    cudaFuncSetAttribute(lstm_mma, cudaFuncAttributeMaxDynamicSharedMemorySize, LSTM_SMEM);
    const int GEMM_SMEM = 65536;
    cudaFuncSetAttribute(gemm_mma<0>, cudaFuncAttributeMaxDynamicSharedMemorySize, GEMM_SMEM);
    cudaFuncSetAttribute(gemm_mma<1>, cudaFuncAttributeMaxDynamicSharedMemorySize, GEMM_SMEM);

    // weight conversions first (inputs only; warms L2)
    cvt_split_b<<<(2048 * 512 + 255) / 256, 256>>>(w_ih, p_wihbf, 2048, 2048);
    cvt_w_f16<<<(VPAD_ * 512 + 255) / 256, 256>>>(fc2_w, p_wf16, VOCAB_, VPAD_);

    // fc1 + fused reduce/bn + embedding
    fc1_part<<<dim3(8, 8), 256>>>(x, fc1_w);
    bn_k<<<EMB_, 64>>>(fc1_b, bn_g, bn_b);
    embed_k<<<(B_ * T_ * (EMB_ / 4) + 255) / 256, 256>>>(y, emb);

    // xW = seq @ w_ih^T + b_ih + b_hh  (bf16 3-term, K'=1536)
    gemm_mma<0><<<dim3(16, 64), 256, GEMM_SMEM>>>((const uint16_t*)p_sbf, (const uint16_t*)p_wihbf,
                                                  b_ih, b_hh, p_xw, 2048, 2048, KSPL_, 0, 0, 0);

    // recurrent LSTM (persistent, 64 blocks x 512 threads)
    zero_k<<<128, 256>>>();
    lstm_mma<<<64, 512, LSTM_SMEM>>>(w_hh, len);

    // out splits for the scores GEMM (parallel)
    cvt_out_k<<<(MS_ * 512 + 255) / 256, 256>>>();

    // attention: scores (batched bf16 3-term) -> fused softmax+AV (fp16 out)
    gemm_mma<0><<<dim3(1, 1, B_), 256, GEMM_SMEM>>>((const uint16_t*)p_oA, (const uint16_t*)p_oB,
                                                    nullptr, nullptr, p_sc, S_, S_, KSPL_,
                                                    (size_t)S_ * KSPL_, (size_t)S_ * KSPL_,
                                                    (size_t)S_ * S_);
    attn_mm<<<dim3(8, B_), 256>>>();

    // predictions = attn @ fc2_w^T + fc2_b  (fp16 single-term, K'=512)
    gemm_mma<1><<<dim3(79, 64), 256, GEMM_SMEM>>>((const uint16_t*)p_af16, (const uint16_t*)p_wf16,
                                                  fc2_b, nullptr, out, VOCAB_, VOCAB_, KF16_, 0, 0, 0);
}

// round 17
// speedup vs baseline: 1.1955x; 1.1955x over previous
#include <cuda_runtime.h>
#include <cuda_bf16.h>
#include <cuda_fp16.h>
#include <math.h>
#include <stdint.h>

#define B_     64
#define T_     127
#define S_     128
#define ENC_   2048
#define EMB_   512
#define HID_   512
#define VOCAB_ 10000
#define MS_    (B_*S_)          // 8192
#define VPAD_  10112            // 79*128
#define KSPL_  1536             // bf16 3-term K'
#define KF16_  512              // fp16 single-term K' (fc2)

// ---------------- static scratch (no cudaMalloc allowed) ----------------
__device__ float g_fc1p[8*B_*EMB_];
__device__ float g_xw  [B_*S_*4*HID_];
__device__ float g_out [B_*S_*HID_];
__device__ float g_sc  [B_*S_*S_];
__device__ unsigned g_bar;
__device__ __nv_bfloat16 g_hh[2][B_*HID_];        // h hi (bf16), double buffered
__device__ __nv_bfloat16 g_hl[2][B_*HID_];        // h lo (bf16)
__device__ __nv_bfloat16 g_sbf  [MS_  * KSPL_];   // seq split   [Ah|Ah|Al]
__device__ __nv_bfloat16 g_wihbf[2048 * KSPL_];   // w_ih split  [Bh|Bl|Bh]
__device__ __nv_bfloat16 g_oA   [MS_  * KSPL_];   // masked out  [Oh|Oh|Ol]
__device__ __nv_bfloat16 g_oB   [MS_  * KSPL_];   // masked out  [Oh|Ol|Oh]
__device__ __half        g_af16 [MS_  * KF16_];   // attn fp16
__device__ __half        g_wf16 [VPAD_* KF16_];   // fc2_w fp16

__device__ __forceinline__ float sigmoidf_(float x) { return 1.f / (1.f + expf(-x)); }

__device__ __forceinline__ uint32_t smem_u32(const void* p) {
    uint32_t a;
    asm("{ .reg .u64 t; cvta.to.shared.u64 t, %1; cvt.u32.u64 %0, t; }" : "=r"(a) : "l"(p));
    return a;
}
__device__ __forceinline__ uint32_t pack_bf2(__nv_bfloat16 a, __nv_bfloat16 b) {
    return ((uint32_t)__bfloat16_as_ushort(b) << 16) | (uint32_t)__bfloat16_as_ushort(a);
}
__device__ __forceinline__ uint32_t pack_hf2(__half a, __half b) {
    return ((uint32_t)__half_as_ushort(b) << 16) | (uint32_t)__half_as_ushort(a);
}
#define CP_ASYNC16(dst, src) asm volatile("cp.async.cg.shared.global [%0], [%1], 16;" :: "r"(dst), "l"(src) : "memory")
#define CP_COMMIT()          asm volatile("cp.async.commit_group;" ::: "memory")
#define CP_WAIT1()           asm volatile("cp.async.wait_group 1;" ::: "memory")
#define CP_WAIT0()           asm volatile("cp.async.wait_group 0;" ::: "memory")

#define MMA_BF16(acc, a0, a1, a2, a3, b0, b1)                                    \
    asm volatile(                                                                \
        "mma.sync.aligned.m16n8k16.row.col.f32.bf16.bf16.f32 "                   \
        "{%0,%1,%2,%3}, {%4,%5,%6,%7}, {%8,%9}, {%0,%1,%2,%3};"                  \
        : "+f"(acc[0]), "+f"(acc[1]), "+f"(acc[2]), "+f"(acc[3])                 \
        : "r"(a0), "r"(a1), "r"(a2), "r"(a3), "r"(b0), "r"(b1))

#define MMA_F16(acc, a0, a1, a2, a3, b0, b1)                                     \
    asm volatile(                                                                \
        "mma.sync.aligned.m16n8k16.row.col.f32.f16.f16.f32 "                     \
        "{%0,%1,%2,%3}, {%4,%5,%6,%7}, {%8,%9}, {%0,%1,%2,%3};"                  \
        : "+f"(acc[0]), "+f"(acc[1]), "+f"(acc[2]), "+f"(acc[3])                 \
        : "r"(a0), "r"(a1), "r"(a2), "r"(a3), "r"(b0), "r"(b1))

// ============ warp-MMA NT GEMM, BK=64, dyn smem 64KB (validated) ==========
template <int FP16>
__global__ __launch_bounds__(256)
void gemm_mma(const uint16_t* __restrict__ A,
              const uint16_t* __restrict__ Bm,
              const float* __restrict__ bias1,
              const float* __restrict__ bias2,
              float* __restrict__ C, int Nreal, int ldc, int kelems,
              size_t sA_, size_t sB_, size_t sC_)
{
    extern __shared__ __align__(16) uint16_t smg[];

    A  += (size_t)blockIdx.z * sA_;
    Bm += (size_t)blockIdx.z * sB_;
    C  += (size_t)blockIdx.z * sC_;

    const int tid  = threadIdx.x;
    const int warp = tid >> 5;
    const int lane = tid & 31;
    const int wm0  = (warp & 3) * 32;
    const int wn0  = (warp >> 2) * 64;
    const int bm   = blockIdx.y * 128;
    const int bn   = blockIdx.x * 128;

    const uint32_t base0 = smem_u32(smg);

    float acc[2][8][4];
#pragma unroll
    for (int mt = 0; mt < 2; mt++)
#pragma unroll
        for (int nt = 0; nt < 8; nt++)
#pragma unroll
            for (int u = 0; u < 4; u++) acc[mt][nt][u] = 0.f;

#define LOAD_TILE(buf, c)                                                        \
    {                                                                            \
        _Pragma("unroll")                                                        \
        for (int u = 0; u < 4; u++) {                                            \
            int idx = tid * 4 + u;                                               \
            int r = idx >> 3, ch = idx & 7;                                      \
            int ph = ch ^ (r & 7);                                               \
            CP_ASYNC16(base0 + (buf) * 32768u + (uint32_t)(r * 8 + ph) * 16,     \
                       A + (size_t)(bm + r) * kelems + (c) * 64 + ch * 8);       \
            CP_ASYNC16(base0 + (buf) * 32768u + 16384u + (uint32_t)(r * 8 + ph) * 16, \
                       Bm + (size_t)(bn + r) * kelems + (c) * 64 + ch * 8);      \
        }                                                                        \
    }

    const int NCH = kelems >> 6;
    LOAD_TILE(0, 0);
    CP_COMMIT();

    for (int c = 0; c < NCH; c++) {
        const int buf = c & 1;
        if (c < NCH - 1) {
            LOAD_TILE(1 - buf, c + 1);
            CP_COMMIT();
            CP_WAIT1();
        } else {
            CP_WAIT0();
        }
        __syncthreads();

        const uint32_t aB = base0 + buf * 32768u;
        const uint32_t bB = aB + 16384u;

#pragma unroll
        for (int kc = 0; kc < 4; kc++) {
            uint32_t afr[2][4], bfr[8][2];
#pragma unroll
            for (int mt = 0; mt < 2; mt++) {
                int row = wm0 + mt * 16 + (lane & 15);
                int ch  = kc * 2 + (lane >> 4);
                int ph  = ch ^ (row & 7);
                uint32_t addr = aB + (uint32_t)(row * 8 + ph) * 16;
                asm volatile("ldmatrix.sync.aligned.m8n8.x4.shared.b16 {%0,%1,%2,%3}, [%4];"
                             : "=r"(afr[mt][0]), "=r"(afr[mt][1]),
                               "=r"(afr[mt][2]), "=r"(afr[mt][3]) : "r"(addr));
            }
#pragma unroll
            for (int nt = 0; nt < 8; nt++) {
                int row = wn0 + nt * 8 + (lane & 7);
                int ch  = kc * 2 + ((lane >> 3) & 1);
                int ph  = ch ^ (row & 7);
                uint32_t addr = bB + (uint32_t)(row * 8 + ph) * 16;
                asm volatile("ldmatrix.sync.aligned.m8n8.x2.shared.b16 {%0,%1}, [%2];"
                             : "=r"(bfr[nt][0]), "=r"(bfr[nt][1]) : "r"(addr));
            }
#pragma unroll
            for (int mt = 0; mt < 2; mt++)
#pragma unroll
                for (int nt = 0; nt < 8; nt++) {
                    if (FP16) {
                        MMA_F16(acc[mt][nt], afr[mt][0], afr[mt][1], afr[mt][2], afr[mt][3],
                                bfr[nt][0], bfr[nt][1]);
                    } else {
                        MMA_BF16(acc[mt][nt], afr[mt][0], afr[mt][1], afr[mt][2], afr[mt][3],
                                 bfr[nt][0], bfr[nt][1]);
                    }
                }
        }
        __syncthreads();
    }

#pragma unroll
    for (int mt = 0; mt < 2; mt++) {
#pragma unroll
        for (int nt = 0; nt < 8; nt++) {
            int row = wm0 + mt * 16 + (lane >> 2);
            int col = wn0 + nt * 8 + (lane & 3) * 2;
            int n = bn + col;
#pragma unroll
            for (int h = 0; h < 2; h++) {
                int m = bm + row + h * 8;
                float vx = acc[mt][nt][h * 2 + 0];
                float vy = acc[mt][nt][h * 2 + 1];
                if (n + 1 < Nreal) {
                    float2 v;
                    v.x = vx; v.y = vy;
                    if (bias1) { v.x += bias1[n]; v.y += bias1[n + 1]; }
                    if (bias2) { v.x += bias2[n]; v.y += bias2[n + 1]; }
                    *(float2*)&C[(size_t)m * ldc + n] = v;
                } else if (n < Nreal) {
                    float v = vx;
                    if (bias1) v += bias1[n];
                    if (bias2) v += bias2[n];
                    C[(size_t)m * ldc + n] = v;
                }
            }
        }
    }
}

// ---------------- bf16 hi/lo split for w_ih ([Bh|Bl|Bh]) ------------------
__global__ void cvt_split_b(const float* __restrict__ src, __nv_bfloat16* __restrict__ dst,
                            int rows_real, int rows_pad)
{
    int i = blockIdx.x * blockDim.x + threadIdx.x;
    if (i >= rows_pad * 512) return;
    int r = i >> 9, k = i & 511;
    float a = (r < rows_real) ? src[(size_t)r * 512 + k] : 0.f;
    __nv_bfloat16 hi = __float2bfloat16(a);
    float lo = a - __bfloat162float(hi);
    size_t b = (size_t)r * KSPL_;
    dst[b + k]        = hi;
    dst[b + 512 + k]  = __float2bfloat16(lo);
    dst[b + 1024 + k] = hi;
}

// ---------------- fp16 weight for fc2 (single copy) -----------------------
__global__ void cvt_w_f16(const float* __restrict__ src, __half* __restrict__ dst,
                          int rows_real, int rows_pad)
{
    int i = blockIdx.x * blockDim.x + threadIdx.x;
    if (i >= rows_pad * 512) return;
    int r = i >> 9, k = i & 511;
    float a = (r < rows_real) ? src[(size_t)r * 512 + k] : 0.f;
    dst[(size_t)r * KF16_ + k] = __float2half(a);
}

// ---------------- out splits for scores GEMM (parallel) -------------------
__global__ void cvt_out_k()
{
    int i = blockIdx.x * blockDim.x + threadIdx.x;
    if (i >= MS_ * 512) return;
    int r = i >> 9, k = i & 511;
    float v = g_out[(size_t)r * 512 + k];
    __nv_bfloat16 hi = __float2bfloat16(v);
    __nv_bfloat16 lo = __float2bfloat16(v - __bfloat162float(hi));
    size_t b = (size_t)r * KSPL_;
    g_oA[b + k]        = hi;
    g_oA[b + 512 + k]  = hi;
    g_oA[b + 1024 + k] = lo;
    g_oB[b + k]        = hi;
    g_oB[b + 512 + k]  = lo;
    g_oB[b + 1024 + k] = hi;
}

// ---------------- fc1 split-K --------------------------------------------
__global__ __launch_bounds__(256)
void fc1_part(const float* __restrict__ x, const float* __restrict__ w)
{
    const int nt = blockIdx.x, kt = blockIdx.y;
    __shared__ float xs[64][68];
    __shared__ float ws[64][68];
    const int tid = threadIdx.x;
    const int ty = tid >> 4, tx = tid & 15;

    float acc[4][4];
#pragma unroll
    for (int i = 0; i < 4; i++)
#pragma unroll
        for (int j = 0; j < 4; j++) acc[i][j] = 0.f;

    for (int kc = 0; kc < 4; kc++) {
        int k0 = kt * 256 + kc * 64;
        for (int i = tid; i < 64 * 16; i += 256) {
            int r = i >> 4, c4 = (i & 15) * 4;
            *(float4*)&xs[r][c4] = *(const float4*)&x[(size_t)r * ENC_ + k0 + c4];
            *(float4*)&ws[r][c4] = *(const float4*)&w[(size_t)(nt * 64 + r) * ENC_ + k0 + c4];
        }
        __syncthreads();
#pragma unroll 8
        for (int k = 0; k < 64; k++) {
            float a[4], b[4];
#pragma unroll
            for (int i = 0; i < 4; i++) a[i] = xs[ty * 4 + i][k];
#pragma unroll
            for (int j = 0; j < 4; j++) b[j] = ws[tx * 4 + j][k];
#pragma unroll
            for (int i = 0; i < 4; i++)
#pragma unroll
                for (int j = 0; j < 4; j++) acc[i][j] += a[i] * b[j];
        }
        __syncthreads();
    }
#pragma unroll
    for (int i = 0; i < 4; i++)
#pragma unroll
        for (int j = 0; j < 4; j++)
            g_fc1p[((size_t)kt * B_ + ty * 4 + i) * EMB_ + nt * 64 + tx * 4 + j] = acc[i][j];
}

// ---------------- fc1 reduce + batchnorm -> seq[:,0,:] split (fused) ------
__global__ void bn_k(const float* __restrict__ b1,
                     const float* __restrict__ gamma, const float* __restrict__ beta)
{
    int j = blockIdx.x;
    int b = threadIdx.x;
    float v = b1[j];
#pragma unroll
    for (int kt = 0; kt < 8; kt++) v += g_fc1p[((size_t)kt * B_ + b) * EMB_ + j];
    __shared__ float s1[64], s2[64];
    s1[b] = v; s2[b] = v * v;
    __syncthreads();
    for (int off = 32; off > 0; off >>= 1) {
        if (b < off) { s1[b] += s1[b + off]; s2[b] += s2[b + off]; }
        __syncthreads();
    }
    float mu  = s1[0] * (1.f / 64.f);
    float var = s2[0] * (1.f / 64.f) - mu * mu;
    float r   = rsqrtf(var + 1e-5f);
    float a   = (v - mu) * r * gamma[j] + beta[j];
    __nv_bfloat16 hi = __float2bfloat16(a);
    __nv_bfloat16 lo = __float2bfloat16(a - __bfloat162float(hi));
    size_t base = (size_t)(b * S_) * KSPL_ + j;
    g_sbf[base]        = hi;
    g_sbf[base + 512]  = hi;
    g_sbf[base + 1024] = lo;
}

// ---------------- embedding gather -> seq split ([Ah|Ah|Al]) --------------
__global__ void embed_k(const int* __restrict__ y, const float* __restrict__ emb)
{
    int i = blockIdx.x * blockDim.x + threadIdx.x;
    if (i >= B_ * T_ * (EMB_ / 4)) return;
    int d4 = i & 127;
    int bt = i >> 7;
    int tt = bt % T_;
    int b  = bt / T_;
    int tok = y[b * T_ + tt];
    float4 v = ((const float4*)emb)[(size_t)tok * (EMB_ / 4) + d4];
    __nv_bfloat16 h0 = __float2bfloat16(v.x), h1 = __float2bfloat16(v.y);
    __nv_bfloat16 h2 = __float2bfloat16(v.z), h3 = __float2bfloat16(v.w);
    uint2 hp, lp;
    hp.x = pack_bf2(h0, h1); hp.y = pack_bf2(h2, h3);
    lp.x = pack_bf2(__float2bfloat16(v.x - __bfloat162float(h0)),
                    __float2bfloat16(v.y - __bfloat162float(h1)));
    lp.y = pack_bf2(__float2bfloat16(v.z - __bfloat162float(h2)),
                    __float2bfloat16(v.w - __bfloat162float(h3)));
    size_t base = (size_t)(b * S_ + 1 + tt) * KSPL_ + d4 * 4;
    *(uint2*)&g_sbf[base]        = hp;
    *(uint2*)&g_sbf[base + 512]  = hp;
    *(uint2*)&g_sbf[base + 1024] = lp;
}

// ---------------- zero h0 (bf16 hi/lo) / barrier --------------------------
__global__ void zero_k()
{
    int i = blockIdx.x * blockDim.x + threadIdx.x;
    if (i < B_ * HID_ / 2) {
        ((uint32_t*)&g_hh[0][0])[i] = 0u;
        ((uint32_t*)&g_hl[0][0])[i] = 0u;
    }
    if (i == 0) g_bar = 0u;
}

// ---------------- persistent LSTM: 128 blocks x 256 threads (validated) ---
#define LW_STRIDE 520
__global__ __launch_bounds__(256)
void lstm_mma(const float* __restrict__ w_hh, const int* __restrict__ lengths)
{
    extern __shared__ __align__(16) char smraw[];
    __nv_bfloat16* Wh = (__nv_bfloat16*)smraw;                  // 16 x 520
    __nv_bfloat16* Wl = Wh + 16 * LW_STRIDE;
    __nv_bfloat16* Ahs = Wl + 16 * LW_STRIDE;                   // 64 x 520
    __nv_bfloat16* Als = Ahs + 64 * LW_STRIDE;
    float* sg = (float*)(Als + 64 * LW_STRIDE);                 // 64 x 17

    const int tid  = threadIdx.x;
    const int warp = tid >> 5;
    const int lane = tid & 31;
    const int j0   = blockIdx.x * 4;

    for (int i = tid; i < 16 * 512; i += 256) {
        int r = i >> 9, k = i & 511;
        int g = r >> 2, jl = r & 3;
        float w = w_hh[(size_t)(g * HID_ + j0 + jl) * HID_ + k];
        __nv_bfloat16 hi = __float2bfloat16(w);
        float lo = w - __bfloat162float(hi);
        Wh[r * LW_STRIDE + k] = hi;
        Wl[r * LW_STRIDE + k] = __float2bfloat16(lo);
    }

    const uint32_t ahA = smem_u32(Ahs), alA = smem_u32(Als);
    const uint32_t whA = smem_u32(Wh),  wlA = smem_u32(Wl);

    const int mt = warp & 3;
    const int nh = warp >> 2;

    const int cb  = tid >> 2;
    const int cj  = tid & 3;
    const int len = lengths[cb];
    float creg = 0.f;

    const float* xwp = g_xw + (size_t)cb * S_ * (4 * HID_) + j0 + cj;

    volatile unsigned* vbar = &g_bar;
    __syncthreads();

    for (int t = 0; t < S_; t++) {
        float xwi = __ldg(xwp + 0 * HID_);
        float xwf = __ldg(xwp + 1 * HID_);
        float xwg = __ldg(xwp + 2 * HID_);
        float xwo = __ldg(xwp + 3 * HID_);
        xwp += 4 * HID_;

        if (tid == 0) {
            unsigned target = 128u * (unsigned)t;
            while (*vbar < target) { }
        }
        __syncthreads();

        const char* hh = (const char*)g_hh[t & 1];
        const char* hl = (const char*)g_hl[t & 1];
#pragma unroll
        for (int u = 0; u < 16; u++) {
            int idx = tid + u * 256;
            int b = idx >> 6, c = idx & 63;
            CP_ASYNC16(ahA + (uint32_t)(b * 65 + c) * 16, hh + b * 1024 + c * 16);
        }
        CP_COMMIT();
#pragma unroll
        for (int u = 0; u < 16; u++) {
            int idx = tid + u * 256;
            int b = idx >> 6, c = idx & 63;
            CP_ASYNC16(alA + (uint32_t)(b * 65 + c) * 16, hl + b * 1024 + c * 16);
        }
        CP_COMMIT();

        float acc[4] = {0.f, 0.f, 0.f, 0.f};

        CP_WAIT1();
        __syncthreads();

        const int arow0 = mt * 16 + (lane & 15);
        const int asel  = lane >> 4;
        const int brow0 = nh * 8 + (lane & 7);
        const int bsel  = (lane >> 3) & 1;

#pragma unroll
        for (int pass = 0; pass < 2; pass++) {
            uint32_t bB = pass ? wlA : whA;
#pragma unroll 8
            for (int kk = 0; kk < 32; kk++) {
                uint32_t a0, a1, a2, a3, b0, b1;
                uint32_t aaddr = ahA + (uint32_t)(arow0 * 65 + kk * 2 + asel) * 16;
                asm volatile("ldmatrix.sync.aligned.m8n8.x4.shared.b16 {%0,%1,%2,%3}, [%4];"
                             : "=r"(a0), "=r"(a1), "=r"(a2), "=r"(a3) : "r"(aaddr));
                uint32_t baddr = bB + (uint32_t)(brow0 * 65 + kk * 2 + bsel) * 16;
                asm volatile("ldmatrix.sync.aligned.m8n8.x2.shared.b16 {%0,%1}, [%2];"
                             : "=r"(b0), "=r"(b1) : "r"(baddr));
                MMA_BF16(acc, a0, a1, a2, a3, b0, b1);
            }
        }

        CP_WAIT0();
        __syncthreads();

#pragma unroll 8
        for (int kk = 0; kk < 32; kk++) {
            uint32_t a0, a1, a2, a3, b0, b1;
            uint32_t aaddr = alA + (uint32_t)(arow0 * 65 + kk * 2 + asel) * 16;
            asm volatile("ldmatrix.sync.aligned.m8n8.x4.shared.b16 {%0,%1,%2,%3}, [%4];"
                         : "=r"(a0), "=r"(a1), "=r"(a2), "=r"(a3) : "r"(aaddr));
            uint32_t baddr = whA + (uint32_t)(brow0 * 65 + kk * 2 + bsel) * 16;
            asm volatile("ldmatrix.sync.aligned.m8n8.x2.shared.b16 {%0,%1}, [%2];"
                         : "=r"(b0), "=r"(b1) : "r"(baddr));
            MMA_BF16(acc, a0, a1, a2, a3, b0, b1);
        }

        {
            int row = mt * 16 + (lane >> 2);
            int col = nh * 8 + (lane & 3) * 2;
            sg[row * 17 + col]           = acc[0];
            sg[row * 17 + col + 1]       = acc[1];
            sg[(row + 8) * 17 + col]     = acc[2];
            sg[(row + 8) * 17 + col + 1] = acc[3];
        }
        __syncthreads();

        {
            float vi = sg[cb * 17 + 0 * 4 + cj] + xwi;
            float vf = sg[cb * 17 + 1 * 4 + cj] + xwf;
            float vg = sg[cb * 17 + 2 * 4 + cj] + xwg;
            float vo = sg[cb * 17 + 3 * 4 + cj] + xwo;
            float gi = sigmoidf_(vi);
            float gf = sigmoidf_(vf);
            float gg = tanhf(vg);
            float go = sigmoidf_(vo);
            float c  = gf * creg + gi * gg;
            creg = c;
            float h = go * tanhf(c);
            int j = j0 + cj;
            g_out[((size_t)cb * S_ + t) * HID_ + j] = (t < len) ? h : 0.f;
            __nv_bfloat16 hi = __float2bfloat16(h);
            float lo = h - __bfloat162float(hi);
            g_hh[(t + 1) & 1][cb * HID_ + j] = hi;
            g_hl[(t + 1) & 1][cb * HID_ + j] = __float2bfloat16(lo);
        }
        __threadfence();
        __syncthreads();
        if (tid == 0) atomicAdd(&g_bar, 1u);
    }
}

// ------- attn: fused masked softmax + AV, writes fp16 for fc2 -------------
__global__ __launch_bounds__(256)
void attn_mm()
{
    int b  = blockIdx.y;
    int t0 = blockIdx.x * 16;
    __shared__ float al[16][128];
    int tid  = threadIdx.x;
    int warp = tid >> 5;
    int lane = tid & 31;

    for (int i = tid; i < 16 * 128; i += 256)
        al[i >> 7][i & 127] = g_sc[((size_t)b * S_ + t0 + (i >> 7)) * S_ + (i & 127)];
    __syncthreads();

#pragma unroll
    for (int rr = 0; rr < 2; rr++) {
        int r = warp * 2 + rr;
        int t = t0 + r;
        float v[4];
#pragma unroll
        for (int u = 0; u < 4; u++) {
            int s = lane + u * 32;
            float x = al[r][s];
            v[u] = (s < t) ? x : 0.f;
        }
        float m = fmaxf(fmaxf(v[0], v[1]), fmaxf(v[2], v[3]));
#pragma unroll
        for (int off = 16; off > 0; off >>= 1)
            m = fmaxf(m, __shfl_xor_sync(0xffffffffu, m, off));
        float e[4], sum = 0.f;
#pragma unroll
        for (int u = 0; u < 4; u++) { e[u] = expf(v[u] - m); sum += e[u]; }
#pragma unroll
        for (int off = 16; off > 0; off >>= 1)
            sum += __shfl_xor_sync(0xffffffffu, sum, off);
        float inv = 1.f / sum;
#pragma unroll
        for (int u = 0; u < 4; u++) {
            int s = lane + u * 32;
            al[r][s] = (s < t) ? e[u] * inv : 0.f;
        }
    }
    __syncthreads();

    int d0 = tid * 2;
    float2 acc[16];
#pragma unroll
    for (int t = 0; t < 16; t++) acc[t] = make_float2(0.f, 0.f);

    for (int s = 0; s < 128; s++) {
        float2 o = *(const float2*)&g_out[((size_t)b * S_ + s) * HID_ + d0];
#pragma unroll
        for (int t = 0; t < 16; t++) {
            float a = al[t][s];
            acc[t].x += a * o.x;
            acc[t].y += a * o.y;
        }
    }
#pragma unroll
    for (int t = 0; t < 16; t++) {
        uint32_t hp = pack_hf2(__float2half(acc[t].x), __float2half(acc[t].y));
        *(uint32_t*)&g_af16[((size_t)b * S_ + t0 + t) * KF16_ + d0] = hp;
    }
}

// ---------------- launch --------------------------------------------------
extern "C" void kernel_launch(void* const* d_in, const int* in_sizes, int n_in,
                              void* d_out, int out_size)
{
    const float* x      = (const float*)d_in[0];
    const int*   y      = (const int*)  d_in[1];
    const int*   len    = (const int*)  d_in[2];
    const float* fc1_w  = (const float*)d_in[3];
    const float* fc1_b  = (const float*)d_in[4];
    const float* bn_g   = (const float*)d_in[5];
    const float* bn_b   = (const float*)d_in[6];
    const float* emb    = (const float*)d_in[7];
    const float* w_ih   = (const float*)d_in[8];
    const float* w_hh   = (const float*)d_in[9];
    const float* b_ih   = (const float*)d_in[10];
    const float* b_hh   = (const float*)d_in[11];
    const float* fc2_w  = (const float*)d_in[12];
    const float* fc2_b  = (const float*)d_in[13];
    float* out = (float*)d_out;

    float *p_xw, *p_sc;
    __nv_bfloat16 *p_sbf, *p_wihbf, *p_oA, *p_oB;
    __half *p_af16, *p_wf16;
    cudaGetSymbolAddress((void**)&p_xw,    g_xw);
    cudaGetSymbolAddress((void**)&p_sc,    g_sc);
    cudaGetSymbolAddress((void**)&p_sbf,   g_sbf);
    cudaGetSymbolAddress((void**)&p_wihbf, g_wihbf);
    cudaGetSymbolAddress((void**)&p_oA,    g_oA);
    cudaGetSymbolAddress((void**)&p_oB,    g_oB);
    cudaGetSymbolAddress((void**)&p_af16,  g_af16);
    cudaGetSymbolAddress((void**)&p_wf16,  g_wf16);

    const int LSTM_SMEM = (16 + 16 + 64 + 64) * LW_STRIDE * 2 + 64 * 17 * 4;
    cudaFuncSetAttribute(lstm_mma, cudaFuncAttributeMaxDynamicSharedMemorySize, LSTM_SMEM);
    const int GEMM_SMEM = 65536;
    cudaFuncSetAttribute(gemm_mma<0>, cudaFuncAttributeMaxDynamicSharedMemorySize, GEMM_SMEM);
    cudaFuncSetAttribute(gemm_mma<1>, cudaFuncAttributeMaxDynamicSharedMemorySize, GEMM_SMEM);

    // weight conversions + state init first (inputs only; warms L2)
    cvt_split_b<<<(2048 * 512 + 255) / 256, 256>>>(w_ih, p_wihbf, 2048, 2048);
    cvt_w_f16<<<(VPAD_ * 512 + 255) / 256, 256>>>(fc2_w, p_wf16, VOCAB_, VPAD_);
    zero_k<<<128, 256>>>();

    // fc1 + fused reduce/bn + embedding
    fc1_part<<<dim3(8, 8), 256>>>(x, fc1_w);
    bn_k<<<EMB_, 64>>>(fc1_b, bn_g, bn_b);
    embed_k<<<(B_ * T_ * (EMB_ / 4) + 255) / 256, 256>>>(y, emb);

    // xW = seq @ w_ih^T + b_ih + b_hh  (bf16 3-term, K'=1536)
    gemm_mma<0><<<dim3(16, 64), 256, GEMM_SMEM>>>((const uint16_t*)p_sbf, (const uint16_t*)p_wihbf,
                                                  b_ih, b_hh, p_xw, 2048, 2048, KSPL_, 0, 0, 0);

    // recurrent LSTM (persistent, 128 blocks x 256 threads)
    lstm_mma<<<128, 256, LSTM_SMEM>>>(w_hh, len);

    // out splits for the scores GEMM (parallel)
    cvt_out_k<<<(MS_ * 512 + 255) / 256, 256>>>();

    // attention: scores (batched bf16 3-term) -> fused softmax+AV (fp16 out)
    gemm_mma<0><<<dim3(1, 1, B_), 256, GEMM_SMEM>>>((const uint16_t*)p_oA, (const uint16_t*)p_oB,
                                                    nullptr, nullptr, p_sc, S_, S_, KSPL_,
                                                    (size_t)S_ * KSPL_, (size_t)S_ * KSPL_,
                                                    (size_t)S_ * S_);
    attn_mm<<<dim3(8, B_), 256>>>();

    // predictions = attn @ fc2_w^T + fc2_b  (fp16 single-term, K'=512)
    gemm_mma<1><<<dim3(79, 64), 256, GEMM_SMEM>>>((const uint16_t*)p_af16, (const uint16_t*)p_wf16,
                                                  fc2_b, nullptr, out, VOCAB_, VOCAB_, KF16_, 0, 0, 0);
}